// round 1
// baseline (speedup 1.0000x reference)
#include <cuda_runtime.h>
#include <math.h>
#include <float.h>

#define BATCH 2
#define NP    32768
#define KNN_TILE 2048
#define PB    64          // stats partial blocks per batch
#define NLEV  4

// ---------------- scratch (device globals; no allocations allowed) ----------
__device__ int   g_idx [NLEV * BATCH * NP * 3];
__device__ float g_w   [NLEV * BATCH * NP * 3];
__device__ float g_psum[BATCH * PB * 256];
__device__ float g_psqs[BATCH * PB * 256];
__device__ float g_mu  [BATCH * 256];
__device__ float g_rstd[BATCH * 256];

// ---------------- fused 4-level exact KNN (K=3) ------------------------------
// One thread per point. Per candidate: screen with s = 0.5|v|^2 - p.v (3 FFMA),
// exact (p-v)^2 recompute on the rare pass path so the selected top-3 set is
// bit-equivalent to the reference's fp32 brute force (margin covers fp32 error
// of the fast form). blockIdx.z reversed so the largest level launches first.
__global__ __launch_bounds__(256) void knn_all_kernel(
    const float* __restrict__ pt,
    const float* __restrict__ vcA, const float* __restrict__ vcB,
    const float* __restrict__ vcC, const float* __restrict__ vcD,
    int nvA, int nvB, int nvC, int nvD)
{
    __shared__ float4 sv[KNN_TILE];

    const int lv = 3 - (int)blockIdx.z;          // 3 (Nv=32768) first
    const float* vc; int Nv;
    switch (lv) {
        case 0:  vc = vcA; Nv = nvA; break;
        case 1:  vc = vcB; Nv = nvB; break;
        case 2:  vc = vcC; Nv = nvC; break;
        default: vc = vcD; Nv = nvD; break;
    }

    const int b = blockIdx.y;
    const int p = blockIdx.x * blockDim.x + threadIdx.x;

    const float* pp3 = pt + ((size_t)b * NP + p) * 3;
    const float px = pp3[0], py = pp3[1], pz = pp3[2];
    const float pp = fmaf(px, px, fmaf(py, py, pz * pz));

    const float* vcb = vc + (size_t)b * Nv * 3;

    float b0 = FLT_MAX, b1 = FLT_MAX, b2 = FLT_MAX;
    int   i0 = 0, i1 = 0, i2 = 0;
    const float MARGIN = 0.0625f;
    float sthr = 0.5f * (b2 + MARGIN - pp);      // screening threshold in s-space

    for (int base = 0; base < Nv; base += KNN_TILE) {
        const int tn = min(KNN_TILE, Nv - base);
        __syncthreads();
        for (int j = threadIdx.x; j < tn; j += blockDim.x) {
            float x = vcb[(base + j) * 3 + 0];
            float y = vcb[(base + j) * 3 + 1];
            float z = vcb[(base + j) * 3 + 2];
            float hv = 0.5f * fmaf(x, x, fmaf(y, y, z * z));
            sv[j] = make_float4(x, y, z, hv);
        }
        __syncthreads();

        #pragma unroll 8
        for (int j = 0; j < tn; j++) {
            float4 v = sv[j];
            float s = fmaf(-px, v.x, v.w);
            s = fmaf(-py, v.y, s);
            s = fmaf(-pz, v.z, s);
            if (s < sthr) {                      // rare path (~30/point)
                float dx = px - v.x, dy = py - v.y, dz = pz - v.z;
                float d2 = fmaf(dx, dx, fmaf(dy, dy, dz * dz));  // exact fp32
                if (d2 < b2) {
                    int idx = base + j;
                    if (d2 < b1) {
                        b2 = b1; i2 = i1;
                        if (d2 < b0) { b1 = b0; i1 = i0; b0 = d2; i0 = idx; }
                        else         { b1 = d2; i1 = idx; }
                    } else { b2 = d2; i2 = idx; }
                    sthr = 0.5f * (b2 + MARGIN - pp);
                }
            }
        }
    }

    // inverse-distance weights, normalized (matches reference: 1/(sqrt(d2)+1e-8))
    float w0 = 1.0f / (sqrtf(b0) + 1e-8f);
    float w1 = 1.0f / (sqrtf(b1) + 1e-8f);
    float w2 = 1.0f / (sqrtf(b2) + 1e-8f);
    float inv = 1.0f / (w0 + w1 + w2);

    size_t o = ((size_t)lv * BATCH * NP + (size_t)b * NP + p) * 3;
    g_idx[o] = i0; g_idx[o + 1] = i1; g_idx[o + 2] = i2;
    g_w[o] = w0 * inv; g_w[o + 1] = w1 * inv; g_w[o + 2] = w2 * inv;
}

// ---------------- interpolation: warp per point, coalesced channel gather ----
__global__ __launch_bounds__(256) void interp_kernel(
    const float* __restrict__ vf, float* __restrict__ out,
    int Nv, int C, int lv)
{
    const int lane = threadIdx.x & 31;
    const int wid  = threadIdx.x >> 5;
    const int p    = blockIdx.x * (blockDim.x >> 5) + wid;
    const int b    = blockIdx.y;

    size_t o = ((size_t)lv * BATCH * NP + (size_t)b * NP + p) * 3;
    int   i0 = g_idx[o], i1 = g_idx[o + 1], i2 = g_idx[o + 2];
    float w0 = g_w[o],   w1 = g_w[o + 1],   w2 = g_w[o + 2];

    const float* f0 = vf + ((size_t)b * Nv + i0) * C;
    const float* f1 = vf + ((size_t)b * Nv + i1) * C;
    const float* f2 = vf + ((size_t)b * Nv + i2) * C;
    float* op = out + ((size_t)b * NP + p) * C;

    for (int c = lane; c < C; c += 32)
        op[c] = fmaf(w2, f2[c], fmaf(w1, f1[c], w0 * f0[c]));
}

// ---------------- BN stats: coalesced per-channel partial sums ---------------
__global__ void stats_partial_kernel(const float* __restrict__ x, int C)
{
    const int c   = threadIdx.x;      // blockDim.x == C
    const int b   = blockIdx.y;
    const int blk = blockIdx.x;       // PB blocks per batch
    const int pn  = NP / PB;

    const float* xb = x + ((size_t)b * NP + (size_t)blk * pn) * C + c;
    float s = 0.f, q = 0.f;
    for (int p = 0; p < pn; p++) {
        float v = xb[(size_t)p * C];
        s += v;
        q = fmaf(v, v, q);
    }
    g_psum[((size_t)b * PB + blk) * C + c] = s;
    g_psqs[((size_t)b * PB + blk) * C + c] = q;
}

__global__ void stats_final_kernel(int C)
{
    int i = blockIdx.x * blockDim.x + threadIdx.x;
    if (i >= BATCH * C) return;
    int b = i / C, c = i % C;
    float s = 0.f, q = 0.f;
    for (int k = 0; k < PB; k++) {
        s += g_psum[((size_t)b * PB + k) * C + c];
        q += g_psqs[((size_t)b * PB + k) * C + c];
    }
    float m   = s * (1.0f / NP);
    float var = q * (1.0f / NP) - m * m;      // biased var, matches jnp.var
    g_mu[b * C + c]   = m;
    g_rstd[b * C + c] = rsqrtf(var + 1e-5f);
}

// ---------------- normalize in place -----------------------------------------
__global__ __launch_bounds__(256) void normalize_kernel(
    float* __restrict__ x,
    const float* __restrict__ gamma, const float* __restrict__ beta, int C)
{
    int i = blockIdx.x * blockDim.x + threadIdx.x;   // within one batch: NP*C
    int b = blockIdx.y;
    int c = i % C;
    size_t idx = (size_t)b * NP * C + i;
    float m = g_mu[b * C + c], r = g_rstd[b * C + c];
    x[idx] = fmaf(gamma[c] * r, x[idx] - m, beta[c]);
}

// ---------------- launch ------------------------------------------------------
extern "C" void kernel_launch(void* const* d_in, const int* in_sizes, int n_in,
                              void* d_out, int out_size)
{
    const float* pt  = (const float*)d_in[0];
    float*       out = (float*)d_out;

    // derive shapes from sizes (B, NP fixed for this problem instance)
    int nv[NLEV], cs[NLEV];
    for (int L = 0; L < NLEV; L++) {
        nv[L] = in_sizes[1 + 4 * L] / (BATCH * 3);
        cs[L] = in_sizes[2 + 4 * L] / (BATCH * nv[L]);
    }

    // fused KNN for all 4 levels (largest level scheduled first)
    knn_all_kernel<<<dim3(NP / 256, BATCH, NLEV), 256>>>(
        pt,
        (const float*)d_in[1], (const float*)d_in[5],
        (const float*)d_in[9], (const float*)d_in[13],
        nv[0], nv[1], nv[2], nv[3]);

    size_t off = 0;
    for (int L = 0; L < NLEV; L++) {
        const float* vf    = (const float*)d_in[2 + 4 * L];
        const float* gamma = (const float*)d_in[3 + 4 * L];
        const float* beta  = (const float*)d_in[4 + 4 * L];
        const int C = cs[L];
        float* o = out + off;

        interp_kernel<<<dim3(NP / 8, BATCH), 256>>>(vf, o, nv[L], C, L);
        stats_partial_kernel<<<dim3(PB, BATCH), C>>>(o, C);
        stats_final_kernel<<<1, 512>>>(C);
        normalize_kernel<<<dim3(NP * C / 256, BATCH), 256>>>(o, gamma, beta, C);

        off += (size_t)BATCH * NP * C;
    }
    (void)n_in; (void)out_size;
}